// round 1
// baseline (speedup 1.0000x reference)
#include <cuda_runtime.h>

// Problem constants
#define NB   4096   // batches
#define NR   200    // query rows per batch
#define DD   64     // embed = hidden = key-len = 64

// Gt[e][j] = 0.125 * sum_h Kw[h][j] * Qw[h][e]   (scale 1/sqrt(64) folded in)
__device__ float g_G[DD * DD];

__global__ void prep_G_kernel(const float* __restrict__ Qw,
                              const float* __restrict__ Kw) {
    int e = blockIdx.x;    // 64 blocks
    int j = threadIdx.x;   // 64 threads
    float acc = 0.f;
#pragma unroll 8
    for (int h = 0; h < DD; ++h)
        acc += Kw[h * DD + j] * Qw[h * DD + e];
    g_G[e * DD + j] = acc * 0.125f;
}

#define TPB 224

__global__ void __launch_bounds__(TPB, 2)
attn_kernel(const float* __restrict__ query,
            const float* __restrict__ key,
            const float* __restrict__ Vw,
            float* __restrict__ out) {
    // key_s: [64][68] padded (272B rows -> 16B aligned, conflict-free LDS.128)
    __shared__ float key_s[DD * 68];
    __shared__ float ct_s[DD * DD];     // Ct[e][m]
    float* vw_s = key_s;                // Vw [h][e] reuses key region after C phase

    const int b   = blockIdx.x;
    const int tid = threadIdx.x;

    // ---- Phase 1a: stage key_b into padded smem ----
    {
        const float4* kg = (const float4*)(key + (size_t)b * DD * DD);
        for (int i = tid; i < DD * DD / 4; i += TPB) {
            int m = i >> 4, j4 = i & 15;
            float4 v = kg[i];
            *(float4*)&key_s[m * 68 + j4 * 4] = v;
        }
    }
    __syncthreads();

    // ---- Phase 1b: Ct[e][m] = sum_j key_s[m][j] * Gt[e][j] ----
    for (int idx = tid; idx < DD * DD; idx += TPB) {
        int e = idx >> 6, m = idx & 63;
        const float4* kr = (const float4*)&key_s[m * 68];
        const float4* gr = (const float4*)&g_G[e * DD];   // broadcast across warp
        float acc = 0.f;
#pragma unroll
        for (int j4 = 0; j4 < 16; ++j4) {
            float4 kv = kr[j4];
            float4 gv = gr[j4];
            acc += kv.x * gv.x + kv.y * gv.y + kv.z * gv.z + kv.w * gv.w;
        }
        ct_s[idx] = acc;   // idx == e*64 + m
    }
    __syncthreads();

    // ---- Phase 1c: stage Vw (row-major [h][e]) into reused region ----
    for (int i = tid; i < DD * DD / 4; i += TPB)
        *(float4*)&vw_s[i * 4] = ((const float4*)Vw)[i];
    __syncthreads();

    // ---- Phase 2: one thread per query row ----
    if (tid < NR) {
        const float4* q4 = (const float4*)(query + ((size_t)b * NR + tid) * DD);

        // logits[m] accumulators
        float acc[DD];
#pragma unroll
        for (int i = 0; i < DD; ++i) acc[i] = 0.f;

#pragma unroll 2
        for (int e4 = 0; e4 < 16; ++e4) {
            float4 qv = q4[e4];          // LDG.128, L1-resident
            float qe[4] = {qv.x, qv.y, qv.z, qv.w};
#pragma unroll
            for (int k = 0; k < 4; ++k) {
                const float4* cr = (const float4*)&ct_s[(e4 * 4 + k) * DD];
                float q_ = qe[k];
#pragma unroll
                for (int m4 = 0; m4 < 16; ++m4) {
                    float4 c = cr[m4];   // broadcast LDS.128 (all lanes same addr)
                    acc[m4 * 4 + 0] += q_ * c.x;
                    acc[m4 * 4 + 1] += q_ * c.y;
                    acc[m4 * 4 + 2] += q_ * c.z;
                    acc[m4 * 4 + 3] += q_ * c.w;
                }
            }
        }

        // per-thread softmax over the 64 logits
        float mx = acc[0];
#pragma unroll
        for (int i = 1; i < DD; ++i) mx = fmaxf(mx, acc[i]);
        float s = 0.f;
#pragma unroll
        for (int i = 0; i < DD; ++i) { acc[i] = __expf(acc[i] - mx); s += acc[i]; }
        float inv = 1.f / s;   // score[i] = acc[i] * inv

        float* orow = out + ((size_t)b * NR + tid) * DD;

        // V projection in 16-wide h chunks, fused gate + store
#pragma unroll 1
        for (int hc = 0; hc < 4; ++hc) {
            float v[16];
#pragma unroll
            for (int i = 0; i < 16; ++i) v[i] = 0.f;
#pragma unroll 4
            for (int e4 = 0; e4 < 16; ++e4) {
                float4 qv = q4[e4];      // L1 hit (re-read)
#pragma unroll
                for (int hh = 0; hh < 16; ++hh) {
                    float4 w = *(const float4*)&vw_s[(hc * 16 + hh) * DD + e4 * 4];
                    v[hh] += qv.x * w.x + qv.y * w.y + qv.z * w.z + qv.w * w.w;
                }
            }
#pragma unroll
            for (int h4 = 0; h4 < 4; ++h4) {
                float4 o;
                o.x = v[h4 * 4 + 0] * acc[hc * 16 + h4 * 4 + 0] * inv;
                o.y = v[h4 * 4 + 1] * acc[hc * 16 + h4 * 4 + 1] * inv;
                o.z = v[h4 * 4 + 2] * acc[hc * 16 + h4 * 4 + 2] * inv;
                o.w = v[h4 * 4 + 3] * acc[hc * 16 + h4 * 4 + 3] * inv;
                *(float4*)&orow[hc * 16 + h4 * 4] = o;
            }
        }
    }
}

extern "C" void kernel_launch(void* const* d_in, const int* in_sizes, int n_in,
                              void* d_out, int out_size) {
    const float* query = (const float*)d_in[0];  // [4096, 200, 64]
    const float* key_t = (const float*)d_in[1];  // [4096, 64, 64]
    const float* Qw    = (const float*)d_in[2];  // [64, 64]
    const float* Kw    = (const float*)d_in[3];  // [64, 64]
    const float* Vw    = (const float*)d_in[4];  // [64, 64]
    float* out = (float*)d_out;                  // [4096, 200, 64]

    prep_G_kernel<<<DD, DD>>>(Qw, Kw);
    attn_kernel<<<NB, TPB>>>(query, key_t, Vw, out);
}

// round 2
// speedup vs baseline: 1.8770x; 1.8770x over previous
#include <cuda_runtime.h>

#define NB   4096
#define NR   200
#define DD   64
#define NCOL 128          // 64 logit cols + 64 V cols
#define TPB  256
#define WS_PAD 132        // W row pitch (floats)
#define RQ_PAD 68         // Q/L/V row pitch (floats), conflict-free row access

// shared-memory regions (float offsets); RA/RC are reused across phases
#define OFF_RA 0                    // Gs (4352) | Qs (8704) | Lsm (8704)
#define OFF_RB 8704                 // Ws: 64 x 132 = 8448
#define OFF_RC (8704 + 8448)        // keys (4352) | Vsm (8704)
#define SMEM_FLOATS (8704 + 8448 + 8704)
#define SMEM_BYTES  (SMEM_FLOATS * 4)

// G[e][j] = 0.125 * sum_h Kw[h][j] * Qw[h][e]
__device__ float g_G[DD * DD];

__global__ void prep_G_kernel(const float* __restrict__ Qw,
                              const float* __restrict__ Kw) {
    int e = blockIdx.x;
    int j = threadIdx.x;
    float acc = 0.f;
#pragma unroll 8
    for (int h = 0; h < DD; ++h)
        acc += Kw[h * DD + j] * Qw[h * DD + e];
    g_G[e * DD + j] = acc * 0.125f;
}

__global__ void __launch_bounds__(TPB, 2)
attn_kernel(const float* __restrict__ query,
            const float* __restrict__ key,
            const float* __restrict__ Vw,
            float* __restrict__ out) {
    extern __shared__ float sm[];
    float* RA = sm + OFF_RA;
    float* ws = sm + OFF_RB;
    float* RC = sm + OFF_RC;

    const int b   = blockIdx.x;
    const int tid = threadIdx.x;
    const int tx  = tid & 15;    // col group: cols tx*8 .. tx*8+7
    const int ty  = tid >> 4;    // row group: rows ty*8 .. ty*8+7

    // ---- Phase 1: stage key_b -> RC, G -> RA (both coalesced, pad 17 float4) ----
    {
        const float4* kg  = (const float4*)(key + (size_t)b * DD * DD);
        float4*       ks4 = (float4*)RC;
        const float4* gg  = (const float4*)g_G;
        float4*       gs4 = (float4*)RA;
        for (int i = tid; i < DD * DD / 4; i += TPB) {
            int r = i >> 4, j4 = i & 15;
            ks4[r * 17 + j4] = kg[i];
            gs4[r * 17 + j4] = gg[i];
        }
    }
    __syncthreads();

    // ---- Phase 2: Ws[e][m] = Ct[e][m] = sum_j key[m][j] * G[e][j] ----
    {
        int e    = tid & 63;          // warp lanes: distinct e -> conflict-free Gs reads
        int msel = tid >> 6;          // 16 m's per thread
        const float4* gr = (const float4*)RA + e * 17;
        const float4* kr = (const float4*)RC;
        float accm[16];
#pragma unroll
        for (int i = 0; i < 16; ++i) accm[i] = 0.f;
#pragma unroll 4
        for (int j4 = 0; j4 < 16; ++j4) {
            float4 gv = gr[j4];
#pragma unroll
            for (int mi = 0; mi < 16; ++mi) {
                float4 kv = kr[(msel * 16 + mi) * 17 + j4];  // broadcast
                accm[mi] += kv.x * gv.x + kv.y * gv.y + kv.z * gv.z + kv.w * gv.w;
            }
        }
        float4* wrow = (float4*)(ws + e * WS_PAD + msel * 16);
#pragma unroll
        for (int m4 = 0; m4 < 4; ++m4)
            wrow[m4] = make_float4(accm[4*m4], accm[4*m4+1], accm[4*m4+2], accm[4*m4+3]);
    }
    // ---- Phase 3: Ws[e][64+h] = Vw[h][e] (transposed stage) ----
    {
        const float4* vg = (const float4*)Vw;
        for (int i = tid; i < DD * DD / 4; i += TPB) {
            int h = i >> 4, e4 = i & 15;
            float4 v = vg[i];
            ws[(e4 * 4 + 0) * WS_PAD + 64 + h] = v.x;
            ws[(e4 * 4 + 1) * WS_PAD + 64 + h] = v.y;
            ws[(e4 * 4 + 2) * WS_PAD + 64 + h] = v.z;
            ws[(e4 * 4 + 3) * WS_PAD + 64 + h] = v.w;
        }
    }
    __syncthreads();

    // ---- Main: two row chunks (128 + 72 rows) ----
#pragma unroll 1
    for (int c = 0; c < 2; ++c) {
        const int r0 = c * 128;
        const int R  = c ? (NR - 128) : 128;

        // stage Q rows [r0, r0+R) -> RA, natural layout [r][e], pad 68
        {
            const float4* qg  = (const float4*)(query + ((size_t)b * NR + r0) * DD);
            float4*       qs4 = (float4*)RA;
            for (int i = tid; i < R * 16; i += TPB) {
                int r = i >> 4, e4 = i & 15;
                qs4[r * 17 + e4] = qg[i];
            }
        }
        __syncthreads();

        float acc[8][8];
#pragma unroll
        for (int i = 0; i < 8; ++i)
#pragma unroll
            for (int j = 0; j < 8; ++j) acc[i][j] = 0.f;

        const bool active = (ty * 8 < R);
        if (active) {
            const float* qrow = RA + (ty * 8) * RQ_PAD;
            const float* wcol = ws + tx * 8;
#pragma unroll 2
            for (int e2 = 0; e2 < 32; ++e2) {
                const int e = e2 * 2;
                float2 a2[8];
#pragma unroll
                for (int i = 0; i < 8; ++i)
                    a2[i] = *(const float2*)&qrow[i * RQ_PAD + e];  // broadcast LDS.64
                float4 b00 = *(const float4*)&wcol[e * WS_PAD];
                float4 b01 = *(const float4*)&wcol[e * WS_PAD + 4];
                float4 b10 = *(const float4*)&wcol[(e + 1) * WS_PAD];
                float4 b11 = *(const float4*)&wcol[(e + 1) * WS_PAD + 4];
#pragma unroll
                for (int i = 0; i < 8; ++i) {
                    float ax = a2[i].x, ay = a2[i].y;
                    acc[i][0] += ax * b00.x;  acc[i][1] += ax * b00.y;
                    acc[i][2] += ax * b00.z;  acc[i][3] += ax * b00.w;
                    acc[i][4] += ax * b01.x;  acc[i][5] += ax * b01.y;
                    acc[i][6] += ax * b01.z;  acc[i][7] += ax * b01.w;
                    acc[i][0] += ay * b10.x;  acc[i][1] += ay * b10.y;
                    acc[i][2] += ay * b10.z;  acc[i][3] += ay * b10.w;
                    acc[i][4] += ay * b11.x;  acc[i][5] += ay * b11.y;
                    acc[i][6] += ay * b11.z;  acc[i][7] += ay * b11.w;
                }
            }
        }
        __syncthreads();   // all Qs reads done; RA can become Lsm

        // epilogue scatter: logits -> Lsm (RA), V -> Vsm (RC)
        float* Lsm = RA;
        float* Vsm = RC;
        if (active) {
#pragma unroll
            for (int i = 0; i < 8; ++i) {
                int r = ty * 8 + i;
                float* dst = (tx < 8) ? (Lsm + r * RQ_PAD + tx * 8)
                                      : (Vsm + r * RQ_PAD + (tx - 8) * 8);
                *(float4*)dst       = make_float4(acc[i][0], acc[i][1], acc[i][2], acc[i][3]);
                *(float4*)(dst + 4) = make_float4(acc[i][4], acc[i][5], acc[i][6], acc[i][7]);
            }
        }
        __syncthreads();

        // softmax + gate: one thread per row (conflict-free pad-68 row reads)
        if (tid < R) {
            float l[64];
            const float4* lr = (const float4*)(Lsm + tid * RQ_PAD);
#pragma unroll
            for (int i = 0; i < 16; ++i) {
                float4 v = lr[i];
                l[4*i] = v.x; l[4*i+1] = v.y; l[4*i+2] = v.z; l[4*i+3] = v.w;
            }
            float mx = l[0];
#pragma unroll
            for (int i = 1; i < 64; ++i) mx = fmaxf(mx, l[i]);
            float s = 0.f;
#pragma unroll
            for (int i = 0; i < 64; ++i) { l[i] = __expf(l[i] - mx); s += l[i]; }
            float inv = 1.f / s;
            float4* vr = (float4*)(Vsm + tid * RQ_PAD);
#pragma unroll
            for (int i = 0; i < 16; ++i) {
                float4 v = vr[i];
                v.x *= l[4*i]   * inv;
                v.y *= l[4*i+1] * inv;
                v.z *= l[4*i+2] * inv;
                v.w *= l[4*i+3] * inv;
                vr[i] = v;
            }
        }
        __syncthreads();

        // coalesced copy Vsm -> out
        {
            float4*       og  = (float4*)(out + ((size_t)b * NR + r0) * DD);
            const float4* vs4 = (const float4*)RC;
            for (int i = tid; i < R * 16; i += TPB) {
                int r = i >> 4, c4 = i & 15;
                og[i] = vs4[r * 17 + c4];
            }
        }
        __syncthreads();
    }
}

extern "C" void kernel_launch(void* const* d_in, const int* in_sizes, int n_in,
                              void* d_out, int out_size) {
    const float* query = (const float*)d_in[0];  // [4096, 200, 64]
    const float* key_t = (const float*)d_in[1];  // [4096, 64, 64]
    const float* Qw    = (const float*)d_in[2];  // [64, 64]
    const float* Kw    = (const float*)d_in[3];  // [64, 64]
    const float* Vw    = (const float*)d_in[4];  // [64, 64]
    float* out = (float*)d_out;                  // [4096, 200, 64]

    cudaFuncSetAttribute(attn_kernel, cudaFuncAttributeMaxDynamicSharedMemorySize, SMEM_BYTES);
    prep_G_kernel<<<DD, DD>>>(Qw, Kw);
    attn_kernel<<<NB, TPB, SMEM_BYTES>>>(query, key_t, Vw, out);
}